// round 17
// baseline (speedup 1.0000x reference)
#include <cuda_runtime.h>
#include <cuda_fp16.h>
#include <math.h>

// Problem constants
constexpr int S   = 1024;   // tokens
constexpr int H   = 2048;   // hidden
constexpr int NH  = 16;     // q heads
constexpr int NKV = 4;      // kv heads
constexpr int D   = 128;    // head dim
constexpr int E   = 64;     // experts
constexpr int TK  = 8;      // top_k
constexpr int IM  = 768;    // moe intermediate
constexpr float EPS = 1e-6f;
constexpr int NA = S * TK;  // total assignments = 8192

// dense GEMM tiling (128x128 CTA tile)
constexpr int KC   = 16;    // K-chunk
constexpr int AST  = 20;    // A smem stride (floats)
constexpr int BSTW = 136;   // dense B smem stride (floats, 128-wide)
constexpr int BST  = 72;    // router B smem stride (floats, 64-wide)
// MoE fp16 tiling
constexpr int MKC  = 32;    // MoE K-chunk (halves)
constexpr int HST  = 40;    // A smem stride (halves)
constexpr int BSH  = 72;    // gu B smem stride (halves, 64-wide)
constexpr int BSHW = 136;   // down B smem stride (halves, 128-wide)
constexpr int MAXT = 200;   // worklist capacity

// ---------------- scratch ----------------
__device__ float g_xnorm [S * H];
__device__ float g_q     [S * NH * D];
__device__ float g_k     [S * NKV * D];
__device__ float g_v     [S * NKV * D];
__device__ float g_ctx   [S * NH * D];
__device__ float g_hid2  [S * H];
__device__ float g_hnorm [S * H];
__device__ __half g_hnorm16[S * H];
__device__ float g_logits[S * E];
__device__ int   g_topk_id[NA];
__device__ float g_topk_w [NA];
__device__ int   g_cnt   [E];
__device__ int   g_off   [E + 1];
__device__ int   g_cur   [E];
__device__ int   g_tok   [NA];
__device__ float g_ew    [NA];
__device__ int   g_pos   [NA];
__device__ int   g_ntile;
__device__ int   g_te    [MAXT];
__device__ int   g_tt    [MAXT];
__device__ __half g_act16 [NA * IM];
__device__ float  g_part  [(size_t)NA * H];
__device__ __align__(16) __half g_w16G[(size_t)E * H * IM];
__device__ __align__(16) __half g_w16U[(size_t)E * H * IM];
__device__ __align__(16) __half g_w16D[(size_t)E * IM * H];

__device__ __forceinline__ float* bufptr(int b) {
    switch (b) {
        case 0: return g_xnorm;
        case 4: return g_ctx;
        case 5: return g_hid2;
        case 6: return g_hnorm;
    }
    return nullptr;
}

// ---------------- helpers ----------------
__device__ __forceinline__ unsigned smaddr(const void* p) {
    return (unsigned)__cvta_generic_to_shared(p);
}
__device__ __forceinline__ unsigned cvt_tf32(float f) {
    unsigned u; asm("cvt.rna.tf32.f32 %0, %1;" : "=r"(u) : "f"(f)); return u;
}
__device__ __forceinline__ void cpa16(unsigned s, const void* g) {
    asm volatile("cp.async.ca.shared.global [%0], [%1], 16;" :: "r"(s), "l"(g));
}
__device__ __forceinline__ void cp_commit() { asm volatile("cp.async.commit_group;"); }
__device__ __forceinline__ void cp_wait0()  { asm volatile("cp.async.wait_group 0;"); }
__device__ __forceinline__ void cp_wait1()  { asm volatile("cp.async.wait_group 1;"); }
__device__ __forceinline__ void ldsm_x4(unsigned r[4], unsigned a) {
    asm volatile("ldmatrix.sync.aligned.m8n8.x4.shared.b16 {%0,%1,%2,%3}, [%4];"
        : "=r"(r[0]), "=r"(r[1]), "=r"(r[2]), "=r"(r[3]) : "r"(a));
}
__device__ __forceinline__ void ldsm_x4_t(unsigned r[4], unsigned a) {
    asm volatile("ldmatrix.sync.aligned.m8n8.x4.trans.shared.b16 {%0,%1,%2,%3}, [%4];"
        : "=r"(r[0]), "=r"(r[1]), "=r"(r[2]), "=r"(r[3]) : "r"(a));
}
__device__ __forceinline__ void mma_tf32(float c[4], const unsigned a[4], const unsigned b[2]) {
    asm volatile(
        "mma.sync.aligned.m16n8k8.row.col.f32.tf32.tf32.f32 "
        "{%0,%1,%2,%3}, {%4,%5,%6,%7}, {%8,%9}, {%0,%1,%2,%3};\n"
        : "+f"(c[0]), "+f"(c[1]), "+f"(c[2]), "+f"(c[3])
        : "r"(a[0]), "r"(a[1]), "r"(a[2]), "r"(a[3]), "r"(b[0]), "r"(b[1]));
}
__device__ __forceinline__ void mma_f16(float c[4], const unsigned a[4], const unsigned b[2]) {
    asm volatile(
        "mma.sync.aligned.m16n8k16.row.col.f32.f16.f16.f32 "
        "{%0,%1,%2,%3}, {%4,%5,%6,%7}, {%8,%9}, {%0,%1,%2,%3};\n"
        : "+f"(c[0]), "+f"(c[1]), "+f"(c[2]), "+f"(c[3])
        : "r"(a[0]), "r"(a[1]), "r"(a[2]), "r"(a[3]), "r"(b[0]), "r"(b[1]));
}

// ---------------- RMSNorm (optionally also writes fp16 copy) ---------------
__global__ void rmsnorm_k(const float* __restrict__ x_ext, int xBuf,
                          const float* __restrict__ g, int outBuf, int alsoHalf) {
    const float* x = x_ext ? x_ext : bufptr(xBuf);
    float* out = bufptr(outBuf);
    int row = blockIdx.x, tid = threadIdx.x;
    const float* xr = x + (size_t)row * H;
    float ss = 0.f;
    for (int j = tid; j < H; j += 256) { float v = xr[j]; ss += v * v; }
    for (int o = 16; o; o >>= 1) ss += __shfl_xor_sync(0xffffffffu, ss, o);
    __shared__ float red[8];
    if ((tid & 31) == 0) red[tid >> 5] = ss;
    __syncthreads();
    if (tid < 32) {
        float v = (tid < 8) ? red[tid] : 0.f;
        for (int o = 4; o; o >>= 1) v += __shfl_xor_sync(0xffffffffu, v, o);
        if (tid == 0) red[0] = v;
    }
    __syncthreads();
    float inv = rsqrtf(red[0] / (float)H + EPS);
    for (int j = tid; j < H; j += 256) {
        float r = xr[j] * inv * g[j];
        out[(size_t)row * H + j] = r;
        if (alsoHalf) g_hnorm16[(size_t)row * H + j] = __float2half(r);
    }
}

// ---------------- weight fp32 -> fp16 convert ------------------------------
__global__ void wconv_k(const float* __restrict__ W, int dstSel) {
    __half* dst = (dstSel == 0) ? g_w16G : (dstSel == 1) ? g_w16U : g_w16D;
    size_t i8 = (size_t)blockIdx.x * 256 + threadIdx.x;
    const float4* src = (const float4*)W + i8 * 2;
    float4 a = src[0], b = src[1];
    __half2 h0 = __floats2half2_rn(a.x, a.y);
    __half2 h1 = __floats2half2_rn(a.z, a.w);
    __half2 h2 = __floats2half2_rn(b.x, b.y);
    __half2 h3 = __floats2half2_rn(b.z, b.w);
    uint4 o;
    o.x = *(unsigned*)&h0; o.y = *(unsigned*)&h1;
    o.z = *(unsigned*)&h2; o.w = *(unsigned*)&h3;
    ((uint4*)dst)[i8] = o;
}

// ---------------- dense TF32 GEMM, 128x128 CTA tile ------------------------
__global__ __launch_bounds__(256) void dense_tf32(int aBuf,
        const float* __restrict__ W0, const float* __restrict__ W1,
        const float* __restrict__ W2, const float* __restrict__ res,
        int mode, int K) {
    const float* A = bufptr(aBuf);
    int m0 = blockIdx.y * 128;
    int n0c = blockIdx.x * 128;
    const float* B; int ldb, nb; float* Cp; int ldo;
    if (mode == 0) {
        if (n0c < 2048)      { B = W0; ldb = 2048; nb = n0c;        Cp = g_q; ldo = 2048; }
        else if (n0c < 2560) { B = W1; ldb = 512;  nb = n0c - 2048; Cp = g_k; ldo = 512; }
        else                 { B = W2; ldb = 512;  nb = n0c - 2560; Cp = g_v; ldo = 512; }
    } else { B = W0; ldb = 2048; nb = n0c; Cp = g_hid2; ldo = 2048; }
    __shared__ __align__(16) float As[2][128 * AST];
    __shared__ __align__(16) float Bs[2][KC * BSTW];
    int tid = threadIdx.x, lane = tid & 31, wid = tid >> 5;
    int wm = wid >> 1, wn = wid & 1;

    auto load_chunk = [&](int k0, int buf) {
        #pragma unroll
        for (int i = 0; i < 2; i++) {
            int id = tid + i * 256;
            int row = id >> 2, q = (id & 3) * 4;
            cpa16(smaddr(&As[buf][row * AST + q]),
                  A + (size_t)(m0 + row) * K + k0 + q);
        }
        #pragma unroll
        for (int i = 0; i < 2; i++) {
            int id = tid + i * 256;
            int kr = id >> 5, nc = (id & 31) * 4;
            cpa16(smaddr(&Bs[buf][kr * BSTW + nc]),
                  B + (size_t)(k0 + kr) * ldb + nb + nc);
        }
        cp_commit();
    };

    float acc[2][8][4] = {};
    int NCH = K / KC;
    load_chunk(0, 0);
    for (int c = 0; c < NCH; c++) {
        int buf = c & 1;
        if (c + 1 < NCH) { load_chunk((c + 1) * KC, buf ^ 1); cp_wait1(); }
        else             { cp_wait0(); }
        __syncthreads();
        #pragma unroll
        for (int ks = 0; ks < 2; ks++) {
            int kk = ks * 8;
            unsigned Af[2][4];
            #pragma unroll
            for (int m = 0; m < 2; m++) {
                const float* ap = &As[buf][(wm * 32 + m * 16 + (lane >> 2)) * AST + kk + (lane & 3)];
                Af[m][0] = cvt_tf32(ap[0]);
                Af[m][1] = cvt_tf32(ap[8 * AST]);
                Af[m][2] = cvt_tf32(ap[4]);
                Af[m][3] = cvt_tf32(ap[8 * AST + 4]);
            }
            #pragma unroll
            for (int nt = 0; nt < 8; nt++) {
                const float* bp = &Bs[buf][(kk + (lane & 3)) * BSTW + wn * 64 + nt * 8 + (lane >> 2)];
                unsigned Bf[2] = { cvt_tf32(bp[0]), cvt_tf32(bp[4 * BSTW]) };
                #pragma unroll
                for (int m = 0; m < 2; m++) mma_tf32(acc[m][nt], Af[m], Bf);
            }
        }
        __syncthreads();
    }
    #pragma unroll
    for (int m = 0; m < 2; m++)
        #pragma unroll
        for (int nt = 0; nt < 8; nt++)
            #pragma unroll
            for (int r = 0; r < 4; r++) {
                int row = m0 + wm * 32 + m * 16 + (lane >> 2) + ((r >= 2) ? 8 : 0);
                int col = wn * 64 + nt * 8 + (lane & 3) * 2 + (r & 1);
                size_t oidx = (size_t)row * ldo + nb + col;
                float v = acc[m][nt][r];
                if (res) v += res[oidx];
                Cp[oidx] = v;
            }
}

// ---------------- router logits GEMM: [S,H] @ [H,E] -> g_logits ------------
// grid (1, 8). CTA tile 128 x 64, tf32 MMA.
__global__ __launch_bounds__(256) void router_gemm(const float* __restrict__ Wg) {
    int m0 = blockIdx.y * 128;
    __shared__ __align__(16) float As[2][128 * AST];
    __shared__ __align__(16) float Bs[2][KC * BST];
    int tid = threadIdx.x, lane = tid & 31, wid = tid >> 5;
    int wm = wid >> 1, wn = wid & 1;

    auto load_chunk = [&](int k0, int buf) {
        #pragma unroll
        for (int i = 0; i < 2; i++) {
            int id = tid + i * 256;
            int row = id >> 2, q = (id & 3) * 4;
            cpa16(smaddr(&As[buf][row * AST + q]),
                  g_hnorm + (size_t)(m0 + row) * H + k0 + q);
        }
        int kr = tid >> 4, nq = (tid & 15) * 4;
        cpa16(smaddr(&Bs[buf][kr * BST + nq]),
              Wg + (size_t)(k0 + kr) * E + nq);
        cp_commit();
    };

    float acc[2][4][4] = {};
    constexpr int NCH = H / KC;
    load_chunk(0, 0);
    for (int c = 0; c < NCH; c++) {
        int buf = c & 1;
        if (c + 1 < NCH) { load_chunk((c + 1) * KC, buf ^ 1); cp_wait1(); }
        else             { cp_wait0(); }
        __syncthreads();
        #pragma unroll
        for (int ks = 0; ks < 2; ks++) {
            int kk = ks * 8;
            unsigned Af[2][4];
            #pragma unroll
            for (int m = 0; m < 2; m++) {
                const float* ap = &As[buf][(wm * 32 + m * 16 + (lane >> 2)) * AST + kk + (lane & 3)];
                Af[m][0] = cvt_tf32(ap[0]);
                Af[m][1] = cvt_tf32(ap[8 * AST]);
                Af[m][2] = cvt_tf32(ap[4]);
                Af[m][3] = cvt_tf32(ap[8 * AST + 4]);
            }
            #pragma unroll
            for (int nt = 0; nt < 4; nt++) {
                const float* bp = &Bs[buf][(kk + (lane & 3)) * BST + wn * 32 + nt * 8 + (lane >> 2)];
                unsigned Bf[2] = { cvt_tf32(bp[0]), cvt_tf32(bp[4 * BST]) };
                #pragma unroll
                for (int m = 0; m < 2; m++) mma_tf32(acc[m][nt], Af[m], Bf);
            }
        }
        __syncthreads();
    }
    #pragma unroll
    for (int m = 0; m < 2; m++)
        #pragma unroll
        for (int nt = 0; nt < 4; nt++)
            #pragma unroll
            for (int r = 0; r < 4; r++) {
                int row = m0 + wm * 32 + m * 16 + (lane >> 2) + ((r >= 2) ? 8 : 0);
                int col = wn * 32 + nt * 8 + (lane & 3) * 2 + (r & 1);
                if (col < E) g_logits[(size_t)row * E + col] = acc[m][nt][r];
            }
}

// ---------------- top-8 select from logits ----------------
__global__ void topk_k() {
    int t = blockIdx.x, tid = threadIdx.x;   // blockDim = 64
    __shared__ float lg[E];
    lg[tid] = g_logits[(size_t)t * E + tid];
    __syncthreads();
    if (tid == 0) {
        float tmp[E];
        for (int e = 0; e < E; e++) tmp[e] = lg[e];
        int   id[TK]; float w[TK];
        for (int k = 0; k < TK; k++) {
            int best = 0; float bv = tmp[0];
            for (int e = 1; e < E; e++) if (tmp[e] > bv) { bv = tmp[e]; best = e; }
            id[k] = best; w[k] = bv; tmp[best] = -1e30f;
        }
        float mx = w[0], s = 0.f;
        for (int k = 0; k < TK; k++) { w[k] = expf(w[k] - mx); s += w[k]; }
        float inv = 1.f / s;
        for (int k = 0; k < TK; k++) {
            g_topk_id[t * TK + k] = id[k];
            g_topk_w [t * TK + k] = w[k] * inv;
            atomicAdd(&g_cnt[id[k]], 1);
        }
    }
}

// ---------------- causal flash attention (fp32) ----------------
__global__ __launch_bounds__(256) void attn_k() {
    constexpr int KT = 32;
    constexpr float SC = 0.0883883476483184f;
    int qt = blockIdx.x, h = blockIdx.y;
    int kvh = h / (NH / NKV);
    int tid = threadIdx.x;
    int qi = tid >> 2, qr = tid & 3;
    int qrow = qt * 64 + qi;
    int d0 = qr * 32;
    __shared__ float Ks[KT][D];
    __shared__ float Vs[KT][D];
    float qreg[32], acc[32];
    #pragma unroll
    for (int d = 0; d < 32; d++) {
        qreg[d] = g_q[(size_t)qrow * (NH * D) + h * D + d0 + d] * SC;
        acc[d] = 0.f;
    }
    float m = -1e30f, l = 0.f;
    int ktiles = qt * 2 + 2;
    for (int kt = 0; kt < ktiles; kt++) {
        int kb = kt * KT;
        for (int idx = tid; idx < KT * D; idx += 256) {
            int r = idx >> 7, c = idx & 127;
            Ks[r][c] = g_k[(size_t)(kb + r) * (NKV * D) + kvh * D + c];
            Vs[r][c] = g_v[(size_t)(kb + r) * (NKV * D) + kvh * D + c];
        }
        __syncthreads();
        float sc[KT];
        #pragma unroll
        for (int j = 0; j < KT; j++) {
            float p = 0.f;
            #pragma unroll
            for (int d = 0; d < 32; d++) p += qreg[d] * Ks[j][d0 + d];
            p += __shfl_xor_sync(0xffffffffu, p, 1);
            p += __shfl_xor_sync(0xffffffffu, p, 2);
            sc[j] = (kb + j <= qrow) ? p : -1e30f;
        }
        float tm = m;
        #pragma unroll
        for (int j = 0; j < KT; j++) tm = fmaxf(tm, sc[j]);
        float corr = __expf(m - tm);
        m = tm;
        l *= corr;
        #pragma unroll
        for (int d = 0; d < 32; d++) acc[d] *= corr;
        #pragma unroll
        for (int j = 0; j < KT; j++) {
            float p = __expf(sc[j] - m);
            l += p;
            #pragma unroll
            for (int d = 0; d < 32; d++) acc[d] += p * Vs[j][d0 + d];
        }
        __syncthreads();
    }
    float inv = 1.f / l;
    #pragma unroll
    for (int d = 0; d < 32; d++)
        g_ctx[(size_t)qrow * (NH * D) + h * D + d0 + d] = acc[d] * inv;
}

// ---------------- dispatch ----------------
__global__ void zero_cnt_k() { if (threadIdx.x < E) g_cnt[threadIdx.x] = 0; }

__global__ void offsets_k() {
    if (threadIdx.x == 0) {
        int run = 0;
        for (int e = 0; e < E; e++) { g_off[e] = run; g_cur[e] = run; run += g_cnt[e]; }
        g_off[E] = run;
        int nt = 0;
        for (int e = 0; e < E; e++) {
            int cnt = g_off[e + 1] - g_off[e];
            for (int t0 = 0; t0 < cnt; t0 += 128) {
                g_te[nt] = e; g_tt[nt] = t0; nt++;
            }
        }
        g_ntile = nt;
    }
}

__global__ void scatter_k() {
    int a = blockIdx.x * blockDim.x + threadIdx.x;
    if (a < NA) {
        int e = g_topk_id[a];
        int pos = atomicAdd(&g_cur[e], 1);
        g_tok[pos] = a >> 3;
        g_ew [pos] = g_topk_w[a];
        g_pos[a]   = pos;
    }
}

// ---------------- MoE gate+up FUSED fp16 GEMM + SwiGLU epilogue ------------
// grid (12, 128): x = n-tile (IM/64), y = worklist tile.
__global__ __launch_bounds__(256) void moe_gu_f16() {
    int ti = blockIdx.y;
    if (ti >= g_ntile) return;
    int e = g_te[ti], t0 = g_tt[ti];
    int base = g_off[e], cnt = g_off[e + 1] - base;
    int i0 = blockIdx.x * 64;
    const __half* WG = g_w16G + (size_t)e * H * IM;
    const __half* WU = g_w16U + (size_t)e * H * IM;
    __shared__ __align__(16) __half As[2][128 * HST];
    __shared__ __align__(16) __half Bg[2][MKC * BSH];
    __shared__ __align__(16) __half Bu[2][MKC * BSH];
    __shared__ int   stok[128];
    __shared__ float swt[128];
    int tid = threadIdx.x, lane = tid & 31, wid = tid >> 5;
    int wm = wid >> 1, wn = wid & 1;
    int lg = lane >> 3, lr8 = lane & 7;
    if (tid < 128) {
        int r = t0 + tid;
        if (r < cnt) { stok[tid] = g_tok[base + r]; swt[tid] = g_ew[base + r]; }
        else         { stok[tid] = g_tok[base]; swt[tid] = 0.f; }
    }
    __syncthreads();

    auto load_chunk = [&](int k0, int buf) {
        #pragma unroll
        for (int i = 0; i < 2; i++) {
            int id = tid + i * 256;
            int row = id >> 2, q = (id & 3) * 8;
            cpa16(smaddr(&As[buf][row * HST + q]),
                  g_hnorm16 + (size_t)stok[row] * H + k0 + q);
        }
        int kr = tid >> 3, q = (tid & 7) * 8;
        cpa16(smaddr(&Bg[buf][kr * BSH + q]), WG + (size_t)(k0 + kr) * IM + i0 + q);
        cpa16(smaddr(&Bu[buf][kr * BSH + q]), WU + (size_t)(k0 + kr) * IM + i0 + q);
        cp_commit();
    };

    float accg[2][4][4] = {};
    float accu[2][4][4] = {};
    constexpr int NCH = H / MKC;   // 64
    load_chunk(0, 0);
    for (int c = 0; c < NCH; c++) {
        int buf = c & 1;
        if (c + 1 < NCH) { load_chunk((c + 1) * MKC, buf ^ 1); cp_wait1(); }
        else             { cp_wait0(); }
        __syncthreads();
        #pragma unroll
        for (int ks = 0; ks < 2; ks++) {
            int kk = ks * 16;
            unsigned Af[2][4];
            #pragma unroll
            for (int m = 0; m < 2; m++) {
                int row = wm * 32 + m * 16 + lr8 + (lg & 1) * 8;
                int col = kk + (lg >> 1) * 8;
                ldsm_x4(Af[m], smaddr(&As[buf][row * HST + col]));
            }
            #pragma unroll
            for (int np = 0; np < 2; np++) {
                int brow = kk + lr8 + (lg & 1) * 8;
                int bcol = wn * 32 + np * 16 + (lg >> 1) * 8;
                unsigned Gf[4], Uf[4];
                ldsm_x4_t(Gf, smaddr(&Bg[buf][brow * BSH + bcol]));
                ldsm_x4_t(Uf, smaddr(&Bu[buf][brow * BSH + bcol]));
                #pragma unroll
                for (int m = 0; m < 2; m++) {
                    mma_f16(accg[m][np * 2 + 0], Af[m], Gf + 0);
                    mma_f16(accg[m][np * 2 + 1], Af[m], Gf + 2);
                    mma_f16(accu[m][np * 2 + 0], Af[m], Uf + 0);
                    mma_f16(accu[m][np * 2 + 1], Af[m], Uf + 2);
                }
            }
        }
        __syncthreads();
    }
    // fused SwiGLU epilogue: act = silu(g)*u*w
    #pragma unroll
    for (int m = 0; m < 2; m++)
        #pragma unroll
        for (int ng = 0; ng < 4; ng++) {
            int rr = wm * 32 + m * 16 + (lane >> 2);
            int colb = wn * 32 + ng * 8 + (lane & 3) * 2;
            #pragma unroll
            for (int hrow = 0; hrow < 2; hrow++) {
                int row = rr + hrow * 8;
                if (t0 + row < cnt) {
                    float w = swt[row];
                    float g0 = accg[m][ng][hrow * 2], g1 = accg[m][ng][hrow * 2 + 1];
                    float u0 = accu[m][ng][hrow * 2], u1 = accu[m][ng][hrow * 2 + 1];
                    float a0 = (g0 / (1.f + __expf(-g0))) * u0 * w;
                    float a1 = (g1 / (1.f + __expf(-g1))) * u1 * w;
                    *(__half2*)&g_act16[(size_t)(base + t0 + row) * IM + i0 + colb] =
                        __floats2half2_rn(a0, a1);
                }
            }
        }
}

// ---------------- MoE down fp16 GEMM, 128x128 tile -------------------------
__global__ __launch_bounds__(256) void moe_down_f16() {
    int ti = blockIdx.y;
    if (ti >= g_ntile) return;
    int e = g_te[ti], t0 = g_tt[ti];
    int base = g_off[e], cnt = g_off[e + 1] - base;
    int h0 = blockIdx.x * 128;
    __shared__ __align__(16) __half As[2][128 * HST];
    __shared__ __align__(16) __half Bs[2][MKC * BSHW];
    int tid = threadIdx.x, lane = tid & 31, wid = tid >> 5;
    int wm = wid >> 1, wn = wid & 1;
    int lg = lane >> 3, lr8 = lane & 7;
    const __half* W16 = g_w16D + (size_t)e * IM * H;

    auto load_chunk = [&](int k0, int buf) {
        #pragma unroll
        for (int i = 0; i < 2; i++) {
            int id = tid + i * 256;
            int row = id >> 2, q = (id & 3) * 8;
            int gr = t0 + row; if (gr >= cnt) gr = cnt - 1;
            cpa16(smaddr(&As[buf][row * HST + q]),
                  g_act16 + (size_t)(base + gr) * IM + k0 + q);
        }
        #pragma unroll
        for (int i = 0; i < 2; i++) {
            int id = tid + i * 256;
            int kr = id >> 4, q = (id & 15) * 8;
            cpa16(smaddr(&Bs[buf][kr * BSHW + q]),
                  W16 + (size_t)(k0 + kr) * H + h0 + q);
        }
        cp_commit();
    };

    float acc[2][8][4] = {};
    constexpr int NCH = IM / MKC;   // 24
    load_chunk(0, 0);
    for (int c = 0; c < NCH; c++) {
        int buf = c & 1;
        if (c + 1 < NCH) { load_chunk((c + 1) * MKC, buf ^ 1); cp_wait1(); }
        else             { cp_wait0(); }
        __syncthreads();
        #pragma unroll
        for (int ks = 0; ks < 2; ks++) {
            int kk = ks * 16;
            unsigned Af[2][4];
            #pragma unroll
            for (int m = 0; m < 2; m++) {
                int row = wm * 32 + m * 16 + lr8 + (lg & 1) * 8;
                int col = kk + (lg >> 1) * 8;
                ldsm_x4(Af[m], smaddr(&As[buf][row * HST + col]));
            }
            #pragma unroll
            for (int np = 0; np < 4; np++) {
                int brow = kk + lr8 + (lg & 1) * 8;
                int bcol = wn * 64 + np * 16 + (lg >> 1) * 8;
                unsigned Bf[4];
                ldsm_x4_t(Bf, smaddr(&Bs[buf][brow * BSHW + bcol]));
                #pragma unroll
                for (int m = 0; m < 2; m++) {
                    mma_f16(acc[m][np * 2 + 0], Af[m], Bf + 0);
                    mma_f16(acc[m][np * 2 + 1], Af[m], Bf + 2);
                }
            }
        }
        __syncthreads();
    }
    #pragma unroll
    for (int m = 0; m < 2; m++)
        #pragma unroll
        for (int ng = 0; ng < 8; ng++) {
            int rr = wm * 32 + m * 16 + (lane >> 2);
            int colb = wn * 64 + ng * 8 + (lane & 3) * 2;
            if (t0 + rr < cnt)
                *(float2*)&g_part[(size_t)(base + t0 + rr) * H + h0 + colb] =
                    make_float2(acc[m][ng][0], acc[m][ng][1]);
            if (t0 + rr + 8 < cnt)
                *(float2*)&g_part[(size_t)(base + t0 + rr + 8) * H + h0 + colb] =
                    make_float2(acc[m][ng][2], acc[m][ng][3]);
        }
}

// ---------------- finalize (vectorized float4) ----------------
__global__ void finalize_k(float* __restrict__ out) {
    size_t i4 = (size_t)blockIdx.x * 256 + threadIdx.x;   // S*H/4 groups
    int t = (int)(i4 / (H / 4));
    int hc = (int)(i4 % (H / 4)) * 4;
    float4 v = *(const float4*)&g_hid2[(size_t)t * H + hc];
    #pragma unroll
    for (int k = 0; k < TK; k++) {
        const float4 p = *(const float4*)&g_part[(size_t)g_pos[t * TK + k] * H + hc];
        v.x += p.x; v.y += p.y; v.z += p.z; v.w += p.w;
    }
    *(float4*)&out[(size_t)t * H + hc] = v;
}

// ---------------- launch ----------------
extern "C" void kernel_launch(void* const* d_in, const int* in_sizes, int n_in,
                              void* d_out, int out_size) {
    const float* hidden = (const float*)d_in[0];
    const float* ln1_g  = (const float*)d_in[1];
    const float* ln2_g  = (const float*)d_in[2];
    const float* Wq     = (const float*)d_in[3];
    const float* Wk     = (const float*)d_in[4];
    const float* Wv     = (const float*)d_in[5];
    const float* Wo     = (const float*)d_in[6];
    const float* Wg     = (const float*)d_in[7];
    const float* Wgate  = (const float*)d_in[8];
    const float* Wup    = (const float*)d_in[9];
    const float* Wdown  = (const float*)d_in[10];
    float* out = (float*)d_out;

    static cudaStream_t s2 = nullptr;
    static cudaEvent_t evFork = nullptr, evJoin = nullptr;
    if (!s2) {
        cudaStreamCreateWithFlags(&s2, cudaStreamNonBlocking);
        cudaEventCreateWithFlags(&evFork, cudaEventDisableTiming);
        cudaEventCreateWithFlags(&evJoin, cudaEventDisableTiming);
    }

    constexpr int WELEMS = E * H * IM;

    // fork: weight conversion on side stream
    cudaEventRecord(evFork, 0);
    cudaStreamWaitEvent(s2, evFork, 0);
    wconv_k<<<WELEMS / 8 / 256, 256, 0, s2>>>(Wgate, 0);
    wconv_k<<<WELEMS / 8 / 256, 256, 0, s2>>>(Wup,   1);
    wconv_k<<<WELEMS / 8 / 256, 256, 0, s2>>>(Wdown, 2);
    cudaEventRecord(evJoin, s2);

    // main pipeline
    rmsnorm_k<<<S, 256>>>(hidden, -1, ln1_g, 0, 0);
    dense_tf32<<<dim3(24, S / 128), 256>>>(0, Wq, Wk, Wv, nullptr, 0, H);
    attn_k<<<dim3(S / 64, NH), 256>>>();
    dense_tf32<<<dim3(16, S / 128), 256>>>(4, Wo, nullptr, nullptr, hidden, 1, NH * D);
    rmsnorm_k<<<S, 256>>>(nullptr, 5, ln2_g, 6, 1);
    zero_cnt_k<<<1, 64>>>();
    router_gemm<<<dim3(1, 8), 256>>>(Wg);
    topk_k<<<S, 64>>>();
    offsets_k<<<1, 1>>>();
    scatter_k<<<(NA + 255) / 256, 256>>>();

    // join: MoE needs the fp16 weights
    cudaStreamWaitEvent(0, evJoin, 0);

    moe_gu_f16<<<dim3(12, 128), 256>>>();
    moe_down_f16<<<dim3(16, 128), 256>>>();
    finalize_k<<<(S * H) / 4 / 256, 256>>>(out);
    (void)in_sizes; (void)n_in; (void)out_size;
}